// round 1
// baseline (speedup 1.0000x reference)
#include <cuda_runtime.h>
#include <cstdint>

#define NPTS 400000
#define CCH  32
#define SX   480
#define SY   360
#define SZ   32
#define BB   2
#define LOOKUP_SIZE (BB*SX*SY*SZ)
#define EPSV 1e-5f

// ---- static scratch (no allocations allowed) ----
__device__ int   d_lookup[LOOKUP_SIZE];   // ~44 MB
__device__ float d_sums[64];              // [0:32) sum, [32:64) sumsq
__device__ float d_scale[CCH];
__device__ float d_shift[CCH];

// ---- packed fp32x2 helpers (sm_100a f32x2 pipe; 2x FFMA throughput) ----
#define FMA2(d, a, b, c) \
    asm("fma.rn.f32x2 %0, %1, %2, %3;" : "=l"(d) : "l"(a), "l"(b), "l"(c))
#define PACK2(d, x) \
    asm("mov.b64 %0, {%1, %1};" : "=l"(d) : "r"(__float_as_uint(x)))
#define UNPACK2(lo, hi, a) \
    asm("mov.b64 {%0, %1}, %2;" : "=r"(lo), "=r"(hi) : "l"(a))

// ============================================================
// 1. clear lookup to -1, zero BN accumulators
// ============================================================
__global__ void clear_kernel() {
    int4* p = (int4*)d_lookup;
    const int n4 = LOOKUP_SIZE / 4;
    int4 v = make_int4(-1, -1, -1, -1);
    for (int i = blockIdx.x * blockDim.x + threadIdx.x; i < n4;
         i += gridDim.x * blockDim.x)
        p[i] = v;
    if (blockIdx.x == 0 && threadIdx.x < 64)
        d_sums[threadIdx.x] = 0.0f;
}

// ============================================================
// 2. scatter point index into dense lookup
// ============================================================
__global__ void scatter_kernel(const int4* __restrict__ coords) {
    int i = blockIdx.x * blockDim.x + threadIdx.x;
    if (i >= NPTS) return;
    int4 c = coords[i];  // (b, c0, c1, c2)
    d_lookup[((c.x * SX + c.y) * SY + c.z) * SZ + c.w] = i;
}

// ============================================================
// 3. sparse conv (9 offsets over d0,d2) + LeakyReLU -> x
// one thread per point; weights in smem; f32x2 accumulators
// ============================================================
__global__ __launch_bounds__(256, 2) void conv_kernel(
    const float* __restrict__ feat,
    const int4*  __restrict__ coords,
    const float* __restrict__ weight,
    float*       __restrict__ xout)
{
    __shared__ unsigned long long w2[9 * 32 * 16];  // 36 KB: W[k][cin][c] as f32x2 pairs
    {
        const unsigned long long* ws = (const unsigned long long*)weight;
        for (int i = threadIdx.x; i < 9 * 32 * 16; i += blockDim.x)
            w2[i] = ws[i];
    }
    __syncthreads();

    int pt = blockIdx.x * blockDim.x + threadIdx.x;
    if (pt >= NPTS) return;

    int4 cc = coords[pt];
    int base = ((cc.x * SX + cc.y) * SY + cc.z) * SZ + cc.w;

    // probe all 9 neighbor cells up-front (MLP over the lookup loads)
    int nbr[9];
#pragma unroll
    for (int k = 0; k < 9; k++) {
        int d0 = k / 3 - 1, d2 = k % 3 - 1;
        int n0 = cc.y + d0, n2 = cc.w + d2;
        bool valid = (n0 >= 0) && (n0 < SX) && (n2 >= 0) && (n2 < SZ);
        int idx = valid ? (base + d0 * (SY * SZ) + d2) : 0;
        int j = __ldg(&d_lookup[idx]);
        nbr[k] = valid ? j : -1;
    }

    unsigned long long acc[16];
#pragma unroll
    for (int q = 0; q < 16; q++) acc[q] = 0ull;

#pragma unroll
    for (int k = 0; k < 9; k++) {
        int jj = nbr[k];
        if (jj >= 0) {
            const float4* fr = (const float4*)(feat + (long long)jj * CCH);
            float4 f0 = __ldg(fr + 0), f1 = __ldg(fr + 1);
            float4 f2 = __ldg(fr + 2), f3 = __ldg(fr + 3);
            float4 f4 = __ldg(fr + 4), f5 = __ldg(fr + 5);
            float4 f6 = __ldg(fr + 6), f7 = __ldg(fr + 7);
            float fv[32] = {
                f0.x, f0.y, f0.z, f0.w, f1.x, f1.y, f1.z, f1.w,
                f2.x, f2.y, f2.z, f2.w, f3.x, f3.y, f3.z, f3.w,
                f4.x, f4.y, f4.z, f4.w, f5.x, f5.y, f5.z, f5.w,
                f6.x, f6.y, f6.z, f6.w, f7.x, f7.y, f7.z, f7.w };
            const unsigned long long* wr = &w2[k * 32 * 16];
#pragma unroll
            for (int cin = 0; cin < 32; cin++) {
                unsigned long long bc;
                PACK2(bc, fv[cin]);
                const ulonglong2* wv = (const ulonglong2*)&wr[cin * 16];
#pragma unroll
                for (int h = 0; h < 8; h++) {
                    ulonglong2 wp = wv[h];  // LDS.128 broadcast
                    FMA2(acc[2 * h],     bc, wp.x, acc[2 * h]);
                    FMA2(acc[2 * h + 1], bc, wp.y, acc[2 * h + 1]);
                }
            }
        }
    }

    // unpack, LeakyReLU (max(v, 0.01v)), store 8x float4
    float4* orow = (float4*)(xout + (long long)pt * CCH);
#pragma unroll
    for (int h = 0; h < 8; h++) {
        unsigned int u0, u1, u2, u3;
        UNPACK2(u0, u1, acc[2 * h]);
        UNPACK2(u2, u3, acc[2 * h + 1]);
        float4 v;
        v.x = __uint_as_float(u0);
        v.y = __uint_as_float(u1);
        v.z = __uint_as_float(u2);
        v.w = __uint_as_float(u3);
        v.x = fmaxf(v.x, 0.01f * v.x);
        v.y = fmaxf(v.y, 0.01f * v.y);
        v.z = fmaxf(v.z, 0.01f * v.z);
        v.w = fmaxf(v.w, 0.01f * v.w);
        orow[h] = v;
    }
}

// ============================================================
// 4. BN reduction: per-channel sum & sumsq (lane = channel)
// ============================================================
__global__ void reduce_kernel(const float* __restrict__ x) {
    int lane  = threadIdx.x & 31;
    int w     = threadIdx.x >> 5;
    int warps = blockDim.x >> 5;
    float s = 0.0f, s2 = 0.0f;
    for (int row = blockIdx.x * warps + w; row < NPTS; row += gridDim.x * warps) {
        float v = __ldg(&x[(long long)row * CCH + lane]);
        s += v;
        s2 = fmaf(v, v, s2);
    }
    __shared__ float ps[16][CCH];
    __shared__ float ps2[16][CCH];
    ps[w][lane]  = s;
    ps2[w][lane] = s2;
    __syncthreads();
    if (w == 0) {
        float t = ps[0][lane], t2 = ps2[0][lane];
        for (int h = 1; h < warps; h++) {
            t  += ps[h][lane];
            t2 += ps2[h][lane];
        }
        atomicAdd(&d_sums[lane],      t);
        atomicAdd(&d_sums[32 + lane], t2);
    }
}

// ============================================================
// 5. finalize: scale = gamma*rsqrt(var+eps), shift = beta - mean*scale
// ============================================================
__global__ void finalize_kernel(const float* __restrict__ gamma,
                                const float* __restrict__ beta) {
    int c = threadIdx.x;
    if (c < CCH) {
        const float invN = 1.0f / (float)NPTS;
        float mean = d_sums[c] * invN;
        float var  = d_sums[32 + c] * invN - mean * mean;
        float sc   = gamma[c] * rsqrtf(var + EPSV);
        d_scale[c] = sc;
        d_shift[c] = beta[c] - mean * sc;
    }
}

// ============================================================
// 6. normalize in place: y = x*scale + shift
// ============================================================
__global__ void norm_kernel(float* __restrict__ y) {
    long long t = (long long)blockIdx.x * blockDim.x + threadIdx.x;
    if (t >= (long long)NPTS * 8) return;
    int q = ((int)t & 7) * 4;
    float4 v = ((float4*)y)[t];
    v.x = v.x * d_scale[q + 0] + d_shift[q + 0];
    v.y = v.y * d_scale[q + 1] + d_shift[q + 1];
    v.z = v.z * d_scale[q + 2] + d_shift[q + 2];
    v.w = v.w * d_scale[q + 3] + d_shift[q + 3];
    ((float4*)y)[t] = v;
}

// ============================================================
extern "C" void kernel_launch(void* const* d_in, const int* in_sizes, int n_in,
                              void* d_out, int out_size) {
    const float* feat   = (const float*)d_in[0];
    const int4*  coords = (const int4*)d_in[1];
    const float* weight = (const float*)d_in[2];
    const float* gamma  = (const float*)d_in[3];
    const float* beta   = (const float*)d_in[4];
    float* out = (float*)d_out;

    clear_kernel<<<2048, 256>>>();
    scatter_kernel<<<(NPTS + 255) / 256, 256>>>(coords);
    conv_kernel<<<(NPTS + 255) / 256, 256>>>(feat, coords, weight, out);
    reduce_kernel<<<592, 256>>>(out);
    finalize_kernel<<<1, 32>>>(gamma, beta);
    norm_kernel<<<(int)(((long long)NPTS * 8 + 255) / 256), 256>>>(out);
}

// round 2
// speedup vs baseline: 2.2206x; 2.2206x over previous
#include <cuda_runtime.h>
#include <cstdint>

#define NPTS 400000
#define CCH  32
#define SX   480
#define SY   360
#define SZ   32
#define BB   2
#define LOOKUP_SIZE (BB*SX*SY*SZ)
#define EPSV 1e-5f

// per-k smem stride in ulonglong units: 512 data + 2 pad (16B) so that
// different-k LDS.128 across divergent lanes hits different banks
#define KSTRIDE 514

// ---- static scratch (no allocations allowed) ----
// zero-initialized at module load; we store (idx+1), 0 == empty, and restore
// zeros each launch via cleanup_kernel -> no 44MB clear needed.
__device__ int   d_lookup[LOOKUP_SIZE];
__device__ float d_sums[64];              // [0:32) sum, [32:64) sumsq (re-zeroed in finalize)
__device__ float d_scale[CCH];
__device__ float d_shift[CCH];

// ---- packed fp32x2 helpers (sm_100a f32x2 pipe; 2x FFMA throughput) ----
#define FMA2(d, a, b, c) \
    asm("fma.rn.f32x2 %0, %1, %2, %3;" : "=l"(d) : "l"(a), "l"(b), "l"(c))
#define PACK2(d, x) \
    asm("mov.b64 %0, {%1, %1};" : "=l"(d) : "r"(__float_as_uint(x)))
#define UNPACK2(lo, hi, a) \
    asm("mov.b64 {%0, %1}, %2;" : "=r"(lo), "=r"(hi) : "l"(a))

// ============================================================
// 1. scatter point index+1 into dense lookup (0 == empty)
// ============================================================
__global__ void scatter_kernel(const int4* __restrict__ coords) {
    int i = blockIdx.x * blockDim.x + threadIdx.x;
    if (i >= NPTS) return;
    int4 c = coords[i];  // (b, c0, c1, c2)
    d_lookup[((c.x * SX + c.y) * SY + c.z) * SZ + c.w] = i + 1;
}

// ============================================================
// helper: accumulate one (in_pt, k) pair into acc (16 x f32x2)
// ============================================================
__device__ __forceinline__ void accum_pair(
    const float* __restrict__ feat, int jj,
    const unsigned long long* wbase,   // smem, k-slice base
    unsigned long long acc[16])
{
    const float4* fr = (const float4*)(feat + (long long)jj * CCH);
    float4 f0 = __ldg(fr + 0), f1 = __ldg(fr + 1);
    float4 f2 = __ldg(fr + 2), f3 = __ldg(fr + 3);
    float4 f4 = __ldg(fr + 4), f5 = __ldg(fr + 5);
    float4 f6 = __ldg(fr + 6), f7 = __ldg(fr + 7);
    float fv[32] = {
        f0.x, f0.y, f0.z, f0.w, f1.x, f1.y, f1.z, f1.w,
        f2.x, f2.y, f2.z, f2.w, f3.x, f3.y, f3.z, f3.w,
        f4.x, f4.y, f4.z, f4.w, f5.x, f5.y, f5.z, f5.w,
        f6.x, f6.y, f6.z, f6.w, f7.x, f7.y, f7.z, f7.w };
#pragma unroll
    for (int cin = 0; cin < 32; cin++) {
        unsigned long long bc;
        PACK2(bc, fv[cin]);
        const ulonglong2* wv = (const ulonglong2*)(wbase + cin * 16);
#pragma unroll
        for (int h = 0; h < 8; h++) {
            ulonglong2 wp = wv[h];
            FMA2(acc[2 * h],     bc, wp.x, acc[2 * h]);
            FMA2(acc[2 * h + 1], bc, wp.y, acc[2 * h + 1]);
        }
    }
}

// ============================================================
// 2. sparse conv (9 offsets over d0,d2) + LeakyReLU -> x
//    self offset processed unconditionally (uniform, broadcast LDS);
//    remaining valid neighbors compacted into a bitmask -> warp executes
//    max-valid iterations (~2.8) instead of any-valid branches (~6.5).
// ============================================================
__global__ __launch_bounds__(256, 2) void conv_kernel(
    const float* __restrict__ feat,
    const int4*  __restrict__ coords,
    const float* __restrict__ weight,
    float*       __restrict__ xout)
{
    __shared__ unsigned long long w2[9 * KSTRIDE];  // ~36.2 KB
    {
        const unsigned long long* ws = (const unsigned long long*)weight;
        for (int i = threadIdx.x; i < 9 * 512; i += blockDim.x) {
            int k = i >> 9;
            int r = i & 511;
            w2[k * KSTRIDE + r] = ws[i];
        }
    }
    __syncthreads();

    int pt = blockIdx.x * blockDim.x + threadIdx.x;
    if (pt >= NPTS) return;

    int4 cc = coords[pt];
    int base = ((cc.x * SX + cc.y) * SY + cc.z) * SZ + cc.w;

    // probe 8 neighbor cells up-front (MLP over the lookup loads)
    unsigned mask = 0;
    int lst[8];
#pragma unroll
    for (int k = 0; k < 9; k++) {
        if (k == 4) continue;
        int d0 = k / 3 - 1, d2 = k % 3 - 1;
        int n0 = cc.y + d0, n2 = cc.w + d2;
        bool valid = (n0 >= 0) && (n0 < SX) && (n2 >= 0) && (n2 < SZ);
        int idx = valid ? (base + d0 * (SY * SZ) + d2) : base;
        int j = __ldg(&d_lookup[idx]);
        j = valid ? j : 0;
        int ki = (k < 4) ? k : k - 1;
        lst[ki] = j - 1;
        if (j > 0) mask |= (1u << ki);
    }

    unsigned long long acc[16];
#pragma unroll
    for (int q = 0; q < 16; q++) acc[q] = 0ull;

    // self offset: k = 4, in_pt = pt. Uniform across warp.
    accum_pair(feat, pt, &w2[4 * KSTRIDE], acc);

    // remaining valid neighbors
    while (mask) {
        int ki = __ffs(mask) - 1;
        mask &= mask - 1;
        int jj = lst[ki];
        int k  = (ki < 4) ? ki : ki + 1;
        accum_pair(feat, jj, &w2[k * KSTRIDE], acc);
    }

    // unpack, LeakyReLU (max(v, 0.01v)), store 8x float4
    float4* orow = (float4*)(xout + (long long)pt * CCH);
#pragma unroll
    for (int h = 0; h < 8; h++) {
        unsigned int u0, u1, u2, u3;
        UNPACK2(u0, u1, acc[2 * h]);
        UNPACK2(u2, u3, acc[2 * h + 1]);
        float4 v;
        v.x = __uint_as_float(u0);
        v.y = __uint_as_float(u1);
        v.z = __uint_as_float(u2);
        v.w = __uint_as_float(u3);
        v.x = fmaxf(v.x, 0.01f * v.x);
        v.y = fmaxf(v.y, 0.01f * v.y);
        v.z = fmaxf(v.z, 0.01f * v.z);
        v.w = fmaxf(v.w, 0.01f * v.w);
        orow[h] = v;
    }
}

// ============================================================
// 3. restore lookup to zero at the touched cells (replaces 44MB clear)
// ============================================================
__global__ void cleanup_kernel(const int4* __restrict__ coords) {
    int i = blockIdx.x * blockDim.x + threadIdx.x;
    if (i >= NPTS) return;
    int4 c = coords[i];
    d_lookup[((c.x * SX + c.y) * SY + c.z) * SZ + c.w] = 0;
}

// ============================================================
// 4. BN reduction: per-channel sum & sumsq, 8 rows in flight per warp
// ============================================================
__global__ void reduce_kernel(const float* __restrict__ x) {
    int lane  = threadIdx.x & 31;
    int w     = threadIdx.x >> 5;
    int gw    = (blockIdx.x * blockDim.x + threadIdx.x) >> 5;
    int nw    = (gridDim.x * blockDim.x) >> 5;
    float s = 0.0f, s2 = 0.0f;
    // NPTS % 8 == 0, and all strides are multiples of 8 -> no tail guard
    for (int r0 = gw * 8; r0 < NPTS; r0 += nw * 8) {
#pragma unroll
        for (int j = 0; j < 8; j++) {
            float v = __ldg(&x[(long long)(r0 + j) * CCH + lane]);
            s += v;
            s2 = fmaf(v, v, s2);
        }
    }
    __shared__ float ps[8][CCH];
    __shared__ float ps2[8][CCH];
    ps[w][lane]  = s;
    ps2[w][lane] = s2;
    __syncthreads();
    if (w == 0) {
        float t = ps[0][lane], t2 = ps2[0][lane];
#pragma unroll
        for (int h = 1; h < 8; h++) {
            t  += ps[h][lane];
            t2 += ps2[h][lane];
        }
        atomicAdd(&d_sums[lane],      t);
        atomicAdd(&d_sums[32 + lane], t2);
    }
}

// ============================================================
// 5. finalize: scale/shift, then re-zero accumulators for next replay
// ============================================================
__global__ void finalize_kernel(const float* __restrict__ gamma,
                                const float* __restrict__ beta) {
    int c = threadIdx.x;
    if (c < CCH) {
        const float invN = 1.0f / (float)NPTS;
        float mean = d_sums[c] * invN;
        float var  = d_sums[32 + c] * invN - mean * mean;
        float sc   = gamma[c] * rsqrtf(var + EPSV);
        d_scale[c] = sc;
        d_shift[c] = beta[c] - mean * sc;
        d_sums[c] = 0.0f;
        d_sums[32 + c] = 0.0f;
    }
}

// ============================================================
// 6. normalize in place: y = x*scale + shift
// ============================================================
__global__ void norm_kernel(float* __restrict__ y) {
    long long t = (long long)blockIdx.x * blockDim.x + threadIdx.x;
    if (t >= (long long)NPTS * 8) return;
    int q = ((int)t & 7) * 4;
    float4 v = ((float4*)y)[t];
    v.x = v.x * d_scale[q + 0] + d_shift[q + 0];
    v.y = v.y * d_scale[q + 1] + d_shift[q + 1];
    v.z = v.z * d_scale[q + 2] + d_shift[q + 2];
    v.w = v.w * d_scale[q + 3] + d_shift[q + 3];
    ((float4*)y)[t] = v;
}

// ============================================================
extern "C" void kernel_launch(void* const* d_in, const int* in_sizes, int n_in,
                              void* d_out, int out_size) {
    const float* feat   = (const float*)d_in[0];
    const int4*  coords = (const int4*)d_in[1];
    const float* weight = (const float*)d_in[2];
    const float* gamma  = (const float*)d_in[3];
    const float* beta   = (const float*)d_in[4];
    float* out = (float*)d_out;

    scatter_kernel<<<(NPTS + 255) / 256, 256>>>(coords);
    conv_kernel<<<(NPTS + 255) / 256, 256>>>(feat, coords, weight, out);
    cleanup_kernel<<<(NPTS + 255) / 256, 256>>>(coords);
    reduce_kernel<<<592, 256>>>(out);
    finalize_kernel<<<1, 32>>>(gamma, beta);
    norm_kernel<<<(int)(((long long)NPTS * 8 + 255) / 256), 256>>>(out);
}

// round 3
// speedup vs baseline: 2.5526x; 1.1495x over previous
#include <cuda_runtime.h>
#include <cstdint>

#define NPTS 400000
#define CCH  32
#define SX   480
#define SY   360
#define SZ   32
#define BB   2
#define LOOKUP_SIZE (BB*SX*SY*SZ)
#define EPSV 1e-5f

// ---- static scratch (no allocations allowed) ----
__device__ int   d_lookup[LOOKUP_SIZE];          // cell -> idx+1, 0 = empty (persistent)
__device__ __align__(16) float d_sums[64];       // [0:32) sum, [32:64) sumsq
__device__ float d_scale[CCH];
__device__ float d_shift[CCH];
__device__ int   d_cnt[8];                       // per-k pair counts (k != 4)
__device__ int2  d_pairs[8][NPTS];               // (out_pt, in_pt) per k

// ---- packed fp32x2 helpers ----
#define FMA2(d, a, b, c) \
    asm("fma.rn.f32x2 %0, %1, %2, %3;" : "=l"(d) : "l"(a), "l"(b), "l"(c))
#define PACK2(d, x) \
    asm("mov.b64 %0, {%1, %1};" : "=l"(d) : "r"(__float_as_uint(x)))
#define UNPACK2(lo, hi, a) \
    asm("mov.b64 {%0, %1}, %2;" : "=r"(lo), "=r"(hi) : "l"(a))

// ============================================================
// GEMV core: acc[16] (f32x2 pairs over 32 couts) += feat_row @ W(smem)
// weights read uniformly per warp -> broadcast LDS (1 phase)
// ============================================================
__device__ __forceinline__ void gemv_accum(
    const float* __restrict__ frow,
    const unsigned long long* __restrict__ wbase,   // smem k-slice
    unsigned long long acc[16])
{
    const float4* fr = (const float4*)frow;
    float4 f0 = __ldg(fr + 0), f1 = __ldg(fr + 1);
    float4 f2 = __ldg(fr + 2), f3 = __ldg(fr + 3);
    float4 f4 = __ldg(fr + 4), f5 = __ldg(fr + 5);
    float4 f6 = __ldg(fr + 6), f7 = __ldg(fr + 7);
    float fv[32] = {
        f0.x, f0.y, f0.z, f0.w, f1.x, f1.y, f1.z, f1.w,
        f2.x, f2.y, f2.z, f2.w, f3.x, f3.y, f3.z, f3.w,
        f4.x, f4.y, f4.z, f4.w, f5.x, f5.y, f5.z, f5.w,
        f6.x, f6.y, f6.z, f6.w, f7.x, f7.y, f7.z, f7.w };
#pragma unroll
    for (int cin = 0; cin < 32; cin++) {
        unsigned long long bc;
        PACK2(bc, fv[cin]);
        const ulonglong2* wv = (const ulonglong2*)(wbase + cin * 16);
#pragma unroll
        for (int h = 0; h < 8; h++) {
            ulonglong2 wp = wv[h];
            FMA2(acc[2 * h],     bc, wp.x, acc[2 * h]);
            FMA2(acc[2 * h + 1], bc, wp.y, acc[2 * h + 1]);
        }
    }
}

// ============================================================
// 1. prep: zero out-buffer, reset pair counters, scatter lookup
// ============================================================
__global__ void prep_kernel(const int4* __restrict__ coords,
                            float4* __restrict__ out4) {
    int i = blockIdx.x * blockDim.x + threadIdx.x;
    if (i < 8) d_cnt[i] = 0;
    const int total4 = NPTS * 8;
    float4 z = make_float4(0.f, 0.f, 0.f, 0.f);
    for (int t = i; t < total4; t += gridDim.x * blockDim.x)
        out4[t] = z;
    if (i < NPTS) {
        int4 c = coords[i];
        d_lookup[((c.x * SX + c.y) * SY + c.z) * SZ + c.w] = i + 1;
    }
}

// ============================================================
// 2. probe: build per-k pair lists (block-aggregated compaction)
// ============================================================
__global__ __launch_bounds__(256) void probe_kernel(const int4* __restrict__ coords) {
    __shared__ int s_wcnt[8][8];   // [ki][warp]
    __shared__ int s_wbase[8][8];
    int tid  = threadIdx.x;
    int lane = tid & 31;
    int warp = tid >> 5;
    int pt = blockIdx.x * 256 + tid;
    bool act = pt < NPTS;

    int4 cc = act ? coords[pt] : make_int4(0, 1, 0, 1);
    int base = ((cc.x * SX + cc.y) * SY + cc.z) * SZ + cc.w;

    unsigned mask = 0;
    int nb[8];
#pragma unroll
    for (int k = 0; k < 9; k++) {
        if (k == 4) continue;
        int d0 = k / 3 - 1, d2 = k % 3 - 1;
        int n0 = cc.y + d0, n2 = cc.w + d2;
        bool valid = act && (n0 >= 0) && (n0 < SX) && (n2 >= 0) && (n2 < SZ);
        int idx = valid ? (base + d0 * (SY * SZ) + d2) : 0;
        int j = valid ? __ldg(&d_lookup[idx]) : 0;
        int ki = (k < 4) ? k : k - 1;
        nb[ki] = j - 1;
        if (j > 0) mask |= (1u << ki);
    }

    unsigned bal[8];
#pragma unroll
    for (int ki = 0; ki < 8; ki++)
        bal[ki] = __ballot_sync(0xffffffffu, (mask >> ki) & 1u);
    if (lane == 0) {
#pragma unroll
        for (int ki = 0; ki < 8; ki++)
            s_wcnt[ki][warp] = __popc(bal[ki]);
    }
    __syncthreads();
    if (tid < 8) {
        int run = 0;
#pragma unroll
        for (int w = 0; w < 8; w++) {
            int c = s_wcnt[tid][w];
            s_wbase[tid][w] = run;
            run += c;
        }
        int g = atomicAdd(&d_cnt[tid], run);
#pragma unroll
        for (int w = 0; w < 8; w++)
            s_wbase[tid][w] += g;
    }
    __syncthreads();
#pragma unroll
    for (int ki = 0; ki < 8; ki++) {
        if ((mask >> ki) & 1u) {
            int rank = __popc(bal[ki] & ((1u << lane) - 1u));
            d_pairs[ki][s_wbase[ki][warp] + rank] = make_int2(pt, nb[ki]);
        }
    }
}

// ============================================================
// 3. neighbor conv: grid.y = ki (8 k's), one thread per pair,
//    uniform-k warps -> broadcast weight LDS; red.v4 accumulate
// ============================================================
__global__ __launch_bounds__(256) void neighbor_kernel(
    const float* __restrict__ feat,
    const float* __restrict__ weight,
    float*       __restrict__ out)
{
    int ki = blockIdx.y;
    int k  = (ki < 4) ? ki : ki + 1;
    __shared__ unsigned long long w2[512];   // 4 KB: W[k]
    {
        const unsigned long long* ws =
            (const unsigned long long*)(weight + k * 1024);
        for (int i = threadIdx.x; i < 512; i += 256)
            w2[i] = ws[i];
    }
    __syncthreads();

    int n = d_cnt[ki];
    for (int p = blockIdx.x * 256 + threadIdx.x; p < n; p += gridDim.x * 256) {
        int2 pr = d_pairs[ki][p];   // (out_pt, in_pt)
        unsigned long long acc[16];
#pragma unroll
        for (int q = 0; q < 16; q++) acc[q] = 0ull;
        gemv_accum(feat + (long long)pr.y * CCH, w2, acc);

        float* orow = out + (long long)pr.x * CCH;
#pragma unroll
        for (int h = 0; h < 8; h++) {
            unsigned int u0, u1, u2, u3;
            UNPACK2(u0, u1, acc[2 * h]);
            UNPACK2(u2, u3, acc[2 * h + 1]);
            asm volatile("red.global.add.v4.f32 [%0], {%1, %2, %3, %4};"
                         :: "l"(orow + 4 * h),
                            "f"(__uint_as_float(u0)), "f"(__uint_as_float(u1)),
                            "f"(__uint_as_float(u2)), "f"(__uint_as_float(u3))
                         : "memory");
        }
    }
}

// ============================================================
// 4. self conv + add neighbor partials + LeakyReLU + BN reduce
// ============================================================
__global__ __launch_bounds__(256, 2) void selfleaky_kernel(
    const float* __restrict__ feat,
    const float* __restrict__ weight,
    float*       __restrict__ out)
{
    __shared__ unsigned long long w2[512];       // 4 KB: W[4]
    __shared__ float s_t[8][32][33];             // transpose tiles, conflict-free
    __shared__ float s_sum[32], s_sq[32];
    {
        const unsigned long long* ws =
            (const unsigned long long*)(weight + 4 * 1024);
        for (int i = threadIdx.x; i < 512; i += 256)
            w2[i] = ws[i];
        if (threadIdx.x < 32) {
            s_sum[threadIdx.x] = 0.0f;
            s_sq[threadIdx.x]  = 0.0f;
        }
    }
    __syncthreads();

    int tid  = threadIdx.x;
    int lane = tid & 31;
    int warp = tid >> 5;
    int pt = blockIdx.x * 256 + tid;
    bool act = pt < NPTS;

    unsigned long long acc[16];
#pragma unroll
    for (int q = 0; q < 16; q++) acc[q] = 0ull;

    float4 part[8];
    if (act) {
        gemv_accum(feat + (long long)pt * CCH, w2, acc);
        const float4* prow = (const float4*)(out + (long long)pt * CCH);
#pragma unroll
        for (int h = 0; h < 8; h++) part[h] = __ldg(prow + h);
    } else {
#pragma unroll
        for (int h = 0; h < 8; h++) part[h] = make_float4(0.f, 0.f, 0.f, 0.f);
    }

    float4 v[8];
#pragma unroll
    for (int h = 0; h < 8; h++) {
        unsigned int u0, u1, u2, u3;
        UNPACK2(u0, u1, acc[2 * h]);
        UNPACK2(u2, u3, acc[2 * h + 1]);
        float4 t;
        t.x = __uint_as_float(u0) + part[h].x;
        t.y = __uint_as_float(u1) + part[h].y;
        t.z = __uint_as_float(u2) + part[h].z;
        t.w = __uint_as_float(u3) + part[h].w;
        t.x = fmaxf(t.x, 0.01f * t.x);
        t.y = fmaxf(t.y, 0.01f * t.y);
        t.z = fmaxf(t.z, 0.01f * t.z);
        t.w = fmaxf(t.w, 0.01f * t.w);
        v[h] = t;
    }

    if (act) {
        float4* orow = (float4*)(out + (long long)pt * CCH);
#pragma unroll
        for (int h = 0; h < 8; h++) orow[h] = v[h];
    }

    // ---- BN reduce: warp-local smem transpose (stride 33, conflict-free) ----
#pragma unroll
    for (int h = 0; h < 8; h++) {
        s_t[warp][lane][4 * h + 0] = v[h].x;
        s_t[warp][lane][4 * h + 1] = v[h].y;
        s_t[warp][lane][4 * h + 2] = v[h].z;
        s_t[warp][lane][4 * h + 3] = v[h].w;
    }
    __syncwarp();
    float s = 0.0f, s2 = 0.0f;
#pragma unroll
    for (int r = 0; r < 32; r++) {
        float x = s_t[warp][r][lane];
        s += x;
        s2 = fmaf(x, x, s2);
    }
    atomicAdd(&s_sum[lane], s);
    atomicAdd(&s_sq[lane],  s2);
    __syncthreads();
    if (tid < 32) {
        atomicAdd(&d_sums[tid],      s_sum[tid]);
        atomicAdd(&d_sums[32 + tid], s_sq[tid]);
    }
}

// ============================================================
// 5. finalize: scale/shift, re-zero accumulators for next replay
// ============================================================
__global__ void finalize_kernel(const float* __restrict__ gamma,
                                const float* __restrict__ beta) {
    int c = threadIdx.x;
    if (c < CCH) {
        const float invN = 1.0f / (float)NPTS;
        float mean = d_sums[c] * invN;
        float var  = d_sums[32 + c] * invN - mean * mean;
        float sc   = gamma[c] * rsqrtf(var + EPSV);
        d_scale[c] = sc;
        d_shift[c] = beta[c] - mean * sc;
        d_sums[c] = 0.0f;
        d_sums[32 + c] = 0.0f;
    }
}

// ============================================================
// 6. normalize in place: y = x*scale + shift
// ============================================================
__global__ void norm_kernel(float* __restrict__ y) {
    int t = blockIdx.x * blockDim.x + threadIdx.x;
    if (t >= NPTS * 8) return;
    int q = (t & 7) * 4;
    float4 v = ((float4*)y)[t];
    v.x = v.x * d_scale[q + 0] + d_shift[q + 0];
    v.y = v.y * d_scale[q + 1] + d_shift[q + 1];
    v.z = v.z * d_scale[q + 2] + d_shift[q + 2];
    v.w = v.w * d_scale[q + 3] + d_shift[q + 3];
    ((float4*)y)[t] = v;
}

// ============================================================
extern "C" void kernel_launch(void* const* d_in, const int* in_sizes, int n_in,
                              void* d_out, int out_size) {
    const float* feat   = (const float*)d_in[0];
    const int4*  coords = (const int4*)d_in[1];
    const float* weight = (const float*)d_in[2];
    const float* gamma  = (const float*)d_in[3];
    const float* beta   = (const float*)d_in[4];
    float* out = (float*)d_out;

    prep_kernel<<<4096, 256>>>(coords, (float4*)out);
    probe_kernel<<<(NPTS + 255) / 256, 256>>>(coords);
    neighbor_kernel<<<dim3(64, 8), 256>>>(feat, weight, out);
    selfleaky_kernel<<<(NPTS + 255) / 256, 256>>>(feat, weight, out);
    finalize_kernel<<<1, 32>>>(gamma, beta);
    norm_kernel<<<(NPTS * 8 + 255) / 256, 256>>>(out);
}